// round 1
// baseline (speedup 1.0000x reference)
#include <cuda_runtime.h>

// ---------------------------------------------------------------------------
// EMD loss, restructured:
//   For each (pair p, batch i): C_i = row-minmax-normalized (1 - cosine(x1[i], x2[i]))
//   E = exp(-2*C_i).  For all 64 "a" at once (batched as 64x64x64 SGEMMs in smem):
//     5x { eu = q1 / (E @ ev)  ;  ev = q2 / (E^T @ eu) }      (2*eps == 1 !)
//   loss(a,i) = sum_jk eu_j * ev_k * E_jk * C_jk
//   output = total_sum / 8192
// ---------------------------------------------------------------------------

#define SMEM_FLOATS 33096
#define SMEM_BYTES (SMEM_FLOATS * 4)

// shared-memory float offsets
#define OFF_X1   0        // 4096  (later: E, row-major [j][k])
#define OFF_X2   4096     // 4160  (stride-65 padded; later: ET [k][j] then GT [k][j], stride 64)
#define OFF_C    8256     // 4096  (C_i row-major [j][k])
#define OFF_CT   12352    // 4096  (C_i transposed [k][j])
#define OFF_Q1   16448    // 4096  (softmax(x1)+1e-12, [a][j]; later T2 [a][j])
#define OFF_Q2   20544    // 4096  (softmax(x2)+1e-12, [a][k])
#define OFF_EU   24640    // 4096  (exp(2u) [a][j])
#define OFF_EV   28736    // 4096  (exp(2v) [a][k])
#define OFF_I1   32832    // 64
#define OFF_I2   32896    // 64
#define OFF_RMIN 32960    // 64
#define OFF_RINV 33024    // 64
#define OFF_RED  33088    // 8

__device__ float g_partials[128];

// acc[f][e] += sum_k A[(a0+f)*64 + k] * B[k*64 + (c0+e)]
// A rows are ty-side (2 distinct rows/warp -> broadcast); B is read contiguously
// along the tile dim (tx side) -> conflict-free float4 LDS on both operands.
__device__ __forceinline__ void tile_gemm(const float* __restrict__ A,
                                          const float* __restrict__ B,
                                          float acc[4][4], int a0, int c0)
{
#pragma unroll 4
    for (int k0 = 0; k0 < 64; k0 += 4) {
        float a_[4][4];
#pragma unroll
        for (int f = 0; f < 4; f++) {
            float4 t = *(const float4*)(A + (a0 + f) * 64 + k0);
            a_[f][0] = t.x; a_[f][1] = t.y; a_[f][2] = t.z; a_[f][3] = t.w;
        }
#pragma unroll
        for (int dk = 0; dk < 4; dk++) {
            float4 b = *(const float4*)(B + (k0 + dk) * 64 + c0);
#pragma unroll
            for (int f = 0; f < 4; f++) {
                acc[f][0] = fmaf(a_[f][dk], b.x, acc[f][0]);
                acc[f][1] = fmaf(a_[f][dk], b.y, acc[f][1]);
                acc[f][2] = fmaf(a_[f][dk], b.z, acc[f][2]);
                acc[f][3] = fmaf(a_[f][dk], b.w, acc[f][3]);
            }
        }
    }
}

__global__ __launch_bounds__(256, 1)
void emd_main(const float* __restrict__ f10, const float* __restrict__ f11,
              const float* __restrict__ f20, const float* __restrict__ f21)
{
    extern __shared__ float sm[];
    const int blk  = blockIdx.x;
    const int pair = blk >> 6;
    const int i    = blk & 63;
    const float* __restrict__ X1g = pair ? f11 : f10;
    const float* __restrict__ X2g = pair ? f21 : f20;

    const int tid  = threadIdx.x;
    const int lane = tid & 31;
    const int wid  = tid >> 5;
    const int ty   = tid >> 4;        // 0..15, a-tile (and j-tile for cosine GEMM)
    const int tx   = tid & 15;        // 0..15, j/k-tile
    const int a0   = ty * 4;
    const int c0   = tx * 4;

    float* sX1 = sm + OFF_X1;
    float* sX2 = sm + OFF_X2;   // stride 65 during cosine phase
    float* sC  = sm + OFF_C;
    float* sCT = sm + OFF_CT;
    float* sQ1 = sm + OFF_Q1;
    float* sQ2 = sm + OFF_Q2;
    float* sEU = sm + OFF_EU;
    float* sEV = sm + OFF_EV;
    float* sI1 = sm + OFF_I1;
    float* sI2 = sm + OFF_I2;
    float* sRmin = sm + OFF_RMIN;
    float* sRinv = sm + OFF_RINV;
    float* sRed  = sm + OFF_RED;

    // ---- load x1[i], x2[i] tiles (x2 padded to stride 65) ----
    {
        const float4* g1 = (const float4*)(X1g + i * 4096);
        const float4* g2 = (const float4*)(X2g + i * 4096);
#pragma unroll
        for (int m = 0; m < 4; m++) {
            int v = tid + m * 256;               // float4 index 0..1023
            float4 a = g1[v];
            ((float4*)sX1)[v] = a;
            float4 b = g2[v];
            int r = v >> 4;
            int c = (v & 15) << 2;
            float* dst = sX2 + r * 65 + c;
            dst[0] = b.x; dst[1] = b.y; dst[2] = b.z; dst[3] = b.w;
        }
    }

    // ---- softmax rows: q = softmax(x[a,i,:]) + 1e-12, for all 64 a ----
#pragma unroll 1
    for (int r8 = 0; r8 < 8; r8++) {
        int a = wid * 8 + r8;
        {
            const float* row = X1g + (a * 64 + i) * 64;
            float x = row[lane], y = row[lane + 32];
            float mx = fmaxf(x, y);
#pragma unroll
            for (int o = 16; o; o >>= 1) mx = fmaxf(mx, __shfl_xor_sync(~0u, mx, o));
            float ex = __expf(x - mx), ey = __expf(y - mx);
            float s = ex + ey;
#pragma unroll
            for (int o = 16; o; o >>= 1) s += __shfl_xor_sync(~0u, s, o);
            float inv = __fdividef(1.0f, s);
            sQ1[a * 64 + lane]      = ex * inv + 1e-12f;
            sQ1[a * 64 + lane + 32] = ey * inv + 1e-12f;
        }
        {
            const float* row = X2g + (a * 64 + i) * 64;
            float x = row[lane], y = row[lane + 32];
            float mx = fmaxf(x, y);
#pragma unroll
            for (int o = 16; o; o >>= 1) mx = fmaxf(mx, __shfl_xor_sync(~0u, mx, o));
            float ex = __expf(x - mx), ey = __expf(y - mx);
            float s = ex + ey;
#pragma unroll
            for (int o = 16; o; o >>= 1) s += __shfl_xor_sync(~0u, s, o);
            float inv = __fdividef(1.0f, s);
            sQ2[a * 64 + lane]      = ex * inv + 1e-12f;
            sQ2[a * 64 + lane + 32] = ey * inv + 1e-12f;
        }
    }
    __syncthreads();

    // ---- inverse clamped row norms ----
#pragma unroll 1
    for (int r8 = 0; r8 < 8; r8++) {
        int row = wid * 8 + r8;
        float x = sX1[row * 64 + lane];
        float y = sX1[row * 64 + 32 + lane];
        float ss = x * x + y * y;
#pragma unroll
        for (int o = 16; o; o >>= 1) ss += __shfl_xor_sync(~0u, ss, o);
        if (lane == 0) sI1[row] = 1.0f / fmaxf(sqrtf(ss), 1e-8f);
        float u = sX2[row * 65 + lane];
        float v = sX2[row * 65 + 32 + lane];
        float ss2 = u * u + v * v;
#pragma unroll
        for (int o = 16; o; o >>= 1) ss2 += __shfl_xor_sync(~0u, ss2, o);
        if (lane == 0) sI2[row] = 1.0f / fmaxf(sqrtf(ss2), 1e-8f);
    }
    __syncthreads();

    // ---- C = 1 - cosine  (GEMM over h; ty->j rows of X1, tx->k rows of X2) ----
    {
        float acc[4][4] = {};
#pragma unroll 2
        for (int h0 = 0; h0 < 64; h0 += 4) {
            float a_[4][4];
#pragma unroll
            for (int f = 0; f < 4; f++) {
                float4 t = *(const float4*)(sX1 + (a0 + f) * 64 + h0);
                a_[f][0] = t.x; a_[f][1] = t.y; a_[f][2] = t.z; a_[f][3] = t.w;
            }
#pragma unroll
            for (int dh = 0; dh < 4; dh++) {
                float b[4];
#pragma unroll
                for (int e = 0; e < 4; e++) b[e] = sX2[(c0 + e) * 65 + h0 + dh];
#pragma unroll
                for (int f = 0; f < 4; f++) {
                    acc[f][0] = fmaf(a_[f][dh], b[0], acc[f][0]);
                    acc[f][1] = fmaf(a_[f][dh], b[1], acc[f][1]);
                    acc[f][2] = fmaf(a_[f][dh], b[2], acc[f][2]);
                    acc[f][3] = fmaf(a_[f][dh], b[3], acc[f][3]);
                }
            }
        }
        float i2v[4];
#pragma unroll
        for (int e = 0; e < 4; e++) i2v[e] = sI2[c0 + e];
#pragma unroll
        for (int f = 0; f < 4; f++) {
            float i1v = sI1[a0 + f];
            float4 r;
            r.x = 1.0f - acc[f][0] * i1v * i2v[0];
            r.y = 1.0f - acc[f][1] * i1v * i2v[1];
            r.z = 1.0f - acc[f][2] * i1v * i2v[2];
            r.w = 1.0f - acc[f][3] * i1v * i2v[3];
            *(float4*)(sC + (a0 + f) * 64 + c0) = r;
        }
    }
    __syncthreads();

    // ---- per-row min/max of C over k ----
#pragma unroll 1
    for (int r8 = 0; r8 < 8; r8++) {
        int row = wid * 8 + r8;
        float x = sC[row * 64 + lane];
        float y = sC[row * 64 + 32 + lane];
        float mn = fminf(x, y), mx = fmaxf(x, y);
#pragma unroll
        for (int o = 16; o; o >>= 1) {
            mn = fminf(mn, __shfl_xor_sync(~0u, mn, o));
            mx = fmaxf(mx, __shfl_xor_sync(~0u, mx, o));
        }
        if (lane == 0) {
            sRmin[row] = mn;
            sRinv[row] = 1.0f / (mx - mn);
        }
    }
    __syncthreads();

    // ---- normalize C; build CT (one-time strided store); E = exp(-2C) into X1 buffer ----
    float* sE = sX1;
#pragma unroll
    for (int m = 0; m < 16; m++) {
        int idx = tid + m * 256;
        int j = idx >> 6, k = idx & 63;
        float cn = (sC[idx] - sRmin[j]) * sRinv[j];
        sC[idx] = cn;
        sCT[k * 64 + j] = cn;
        sE[idx] = __expf(-2.0f * cn);
    }
    __syncthreads();

    // ---- ET from CT (coalesced); init ev = 1 ----
    float* sET = sX2;   // reuse X2 buffer, flat stride-64 layout now
#pragma unroll
    for (int m = 0; m < 16; m++) {
        int idx = tid + m * 256;
        sET[idx] = __expf(-2.0f * sCT[idx]);
        sEV[idx] = 1.0f;
    }
    __syncthreads();

    // ---- Sinkhorn: 5 Gauss-Seidel iterations, multiplicative form ----
#pragma unroll 1
    for (int it = 0; it < 5; it++) {
        {   // u-phase: S[a][j] = sum_k EV[a][k] * ET[k][j];  EU = Q1 / S
            float acc[4][4] = {};
            tile_gemm(sEV, sET, acc, a0, c0);
#pragma unroll
            for (int f = 0; f < 4; f++) {
                float4 q = *(const float4*)(sQ1 + (a0 + f) * 64 + c0);
                float4 r;
                r.x = __fdividef(q.x, acc[f][0]);
                r.y = __fdividef(q.y, acc[f][1]);
                r.z = __fdividef(q.z, acc[f][2]);
                r.w = __fdividef(q.w, acc[f][3]);
                *(float4*)(sEU + (a0 + f) * 64 + c0) = r;
            }
        }
        __syncthreads();
        {   // v-phase: T[a][k] = sum_j EU[a][j] * E[j][k];  EV = Q2 / T
            float acc[4][4] = {};
            tile_gemm(sEU, sE, acc, a0, c0);
#pragma unroll
            for (int f = 0; f < 4; f++) {
                float4 q = *(const float4*)(sQ2 + (a0 + f) * 64 + c0);
                float4 r;
                r.x = __fdividef(q.x, acc[f][0]);
                r.y = __fdividef(q.y, acc[f][1]);
                r.z = __fdividef(q.z, acc[f][2]);
                r.w = __fdividef(q.w, acc[f][3]);
                *(float4*)(sEV + (a0 + f) * 64 + c0) = r;
            }
        }
        __syncthreads();
    }

    // ---- final: GT[k][j] = ET*CT (in place); T2[a][j] = sum_k EV[a][k]*GT[k][j] ----
#pragma unroll
    for (int m = 0; m < 16; m++) {
        int idx = tid + m * 256;
        sET[idx] *= sCT[idx];
    }
    __syncthreads();
    {
        float acc[4][4] = {};
        tile_gemm(sEV, sET, acc, a0, c0);
#pragma unroll
        for (int f = 0; f < 4; f++) {
            float4 r;
            r.x = acc[f][0]; r.y = acc[f][1]; r.z = acc[f][2]; r.w = acc[f][3];
            *(float4*)(sQ1 + (a0 + f) * 64 + c0) = r;   // Q1 buffer now holds T2
        }
    }
    __syncthreads();

    // ---- loss partial: sum_{a,j} EU[a][j] * T2[a][j] ----
    float local = 0.0f;
#pragma unroll
    for (int m = 0; m < 16; m++) {
        int idx = tid + m * 256;
        local = fmaf(sEU[idx], sQ1[idx], local);
    }
#pragma unroll
    for (int o = 16; o; o >>= 1) local += __shfl_xor_sync(~0u, local, o);
    if (lane == 0) sRed[wid] = local;
    __syncthreads();
    if (tid == 0) {
        float t = 0.0f;
#pragma unroll
        for (int w = 0; w < 8; w++) t += sRed[w];
        g_partials[blk] = t;
    }
}

__global__ void emd_reduce(float* __restrict__ out)
{
    float v = g_partials[threadIdx.x];   // 128 threads
#pragma unroll
    for (int o = 16; o; o >>= 1) v += __shfl_xor_sync(~0u, v, o);
    __shared__ float s[4];
    if ((threadIdx.x & 31) == 0) s[threadIdx.x >> 5] = v;
    __syncthreads();
    if (threadIdx.x == 0)
        out[0] = (s[0] + s[1] + s[2] + s[3]) * (1.0f / 8192.0f);
}

extern "C" void kernel_launch(void* const* d_in, const int* in_sizes, int n_in,
                              void* d_out, int out_size)
{
    (void)in_sizes; (void)n_in; (void)out_size;
    cudaFuncSetAttribute(emd_main, cudaFuncAttributeMaxDynamicSharedMemorySize, SMEM_BYTES);
    emd_main<<<128, 256, SMEM_BYTES>>>((const float*)d_in[0], (const float*)d_in[1],
                                       (const float*)d_in[2], (const float*)d_in[3]);
    emd_reduce<<<1, 128>>>((float*)d_out);
}